// round 1
// baseline (speedup 1.0000x reference)
#include <cuda_runtime.h>

#define OUT_S 56
#define N_OUT (OUT_S * OUT_S)     // 3136
#define N_OUT4 (N_OUT / 4)        // 784
#define NC_PER_GROUP 8192         // 32 patches * 256 channels

__global__ __launch_bounds__(256)
void denorm_relu_pool_kernel(const float* __restrict__ p24,
                             const float* __restrict__ p32,
                             const float* __restrict__ p48,
                             const float* __restrict__ smean,
                             const float* __restrict__ sstd,
                             float* __restrict__ out)
{
    __shared__ float tile[48 * 48];      // max side 48 -> 2304 floats (9.2 KB)
    __shared__ int   tstart[OUT_S];
    __shared__ int   twid[OUT_S];
    __shared__ float tinv[OUT_S];

    const int gnc = blockIdx.x;          // 0..24575, == global (n*256 + c)
    const int grp = gnc / NC_PER_GROUP;  // 0,1,2
    const int tid = threadIdx.x;

    int s;
    const float* src;
    if (grp == 0)      { s = 24; src = p24; }
    else if (grp == 1) { s = 32; src = p32; }
    else               { s = 48; src = p48; }
    const int local = gnc - grp * NC_PER_GROUP;

    // Per-(patch,channel) affine params. Group concat order of style_mean/std
    // matches the block ordering, so gnc indexes directly.
    const float mean = smean[gnc];
    const float sd   = sstd[gnc];

    // Adaptive-pool LUT: window start, width (1 or 2 since s < 56), 1/width.
    if (tid < OUT_S) {
        int s0 = (tid * s) / OUT_S;
        int e  = ((tid + 1) * s + (OUT_S - 1)) / OUT_S;  // ceil((i+1)*s/56)
        tstart[tid] = s0;
        int w = e - s0;
        twid[tid] = w;
        tinv[tid] = 1.0f / (float)w;
    }

    // Stream the tile in, fusing denorm + ReLU. s*s is divisible by 4 for all sides.
    const int n2 = s * s;
    const int n4 = n2 >> 2;
    const float4* __restrict__ src4 =
        (const float4*)(src + (size_t)local * (size_t)n2);
    float4* tile4 = (float4*)tile;
    for (int k = tid; k < n4; k += 256) {
        float4 v = src4[k];
        v.x = fmaxf(fmaf(v.x, sd, mean), 0.0f);
        v.y = fmaxf(fmaf(v.y, sd, mean), 0.0f);
        v.z = fmaxf(fmaf(v.z, sd, mean), 0.0f);
        v.w = fmaxf(fmaf(v.w, sd, mean), 0.0f);
        tile4[k] = v;
    }
    __syncthreads();

    float4* __restrict__ dst4 = (float4*)(out + (size_t)gnc * (size_t)N_OUT);

    // 784 float4 outputs per block; 56 % 4 == 0 so each float4 stays in one row.
    for (int k4 = tid; k4 < N_OUT4; k4 += 256) {
        const int i  = k4 / (OUT_S / 4);               // output row
        const int j0 = (k4 - i * (OUT_S / 4)) * 4;     // first output col
        const int r0   = tstart[i];
        const bool wi2 = (twid[i] == 2);
        const float ri = tinv[i];
        const float* rowa = tile + r0 * s;

        float4 v;
        float* vp = &v.x;
        #pragma unroll
        for (int q = 0; q < 4; q++) {
            const int j  = j0 + q;
            const int c0 = tstart[j];
            const bool wj2 = (twid[j] == 2);
            float acc = rowa[c0];
            if (wj2) acc += rowa[c0 + 1];
            if (wi2) {
                acc += rowa[s + c0];
                if (wj2) acc += rowa[s + c0 + 1];
            }
            vp[q] = acc * (ri * tinv[j]);
        }
        dst4[k4] = v;
    }
}

extern "C" void kernel_launch(void* const* d_in, const int* in_sizes, int n_in,
                              void* d_out, int out_size)
{
    const float* p24   = (const float*)d_in[0];
    const float* p32   = (const float*)d_in[1];
    const float* p48   = (const float*)d_in[2];
    const float* smean = (const float*)d_in[3];
    const float* sstd  = (const float*)d_in[4];
    float* out = (float*)d_out;

    denorm_relu_pool_kernel<<<3 * NC_PER_GROUP, 256>>>(p24, p32, p48,
                                                       smean, sstd, out);
}

// round 2
// speedup vs baseline: 1.5895x; 1.5895x over previous
#include <cuda_runtime.h>

#define OUT_S 56
#define N_OUT 3136            // 56*56
#define N_OUT4 784            // float4 outputs per (patch,channel)
#define NC_PER_GROUP 8192     // 32 patches * 256 channels

// Separable adaptive pool: every S in {24,32,48} < 56, so windows are 1 or 2 wide.
// S/56 reduces to NUM/7 with NUM = S/8; window pattern has period 7 and
// 14 output cols map to exactly S/4 contiguous input cols per quarter.

template<int S>
__device__ __forceinline__ void run_group(const float* __restrict__ src,
                                          float mean, float sd,
                                          float* __restrict__ hp,     // [S+1][56]
                                          float* __restrict__ outp,   // 3136 floats
                                          int tid)
{
    constexpr int NUM = S / 8;     // 3, 4, 6
    constexpr int CPT = S / 4;     // input cols per thread: 6, 8, 12

    // Zero the pad row (row S) so phase B can always read r0+1 safely.
    if (tid < 14) {
        ((float4*)(hp + S * 56))[tid] = make_float4(0.f, 0.f, 0.f, 0.f);
    }

    // ---------------- Phase A: horizontal pool (global -> smem) ----------------
    if (tid < S * 4) {
        const int r = tid >> 2;
        const int q = tid & 3;
        const float* __restrict__ row = src + r * S + q * CPT;

        float v[CPT];
        if constexpr ((CPT & 3) == 0) {
            #pragma unroll
            for (int k = 0; k < CPT / 4; k++) {
                float4 t = ((const float4*)row)[k];
                v[4*k+0] = t.x; v[4*k+1] = t.y; v[4*k+2] = t.z; v[4*k+3] = t.w;
            }
        } else {
            #pragma unroll
            for (int k = 0; k < CPT / 2; k++) {
                float2 t = ((const float2*)row)[k];
                v[2*k+0] = t.x; v[2*k+1] = t.y;
            }
        }
        #pragma unroll
        for (int k = 0; k < CPT; k++)
            v[k] = fmaxf(fmaf(v[k], sd, mean), 0.0f);

        // 14 horizontally-pooled outputs; window geometry is compile-time.
        float o[14];
        #pragma unroll
        for (int jr = 0; jr < 14; jr++) {
            const int c0 = (jr * NUM) / 7;
            const int w  = ((jr + 1) * NUM + 6) / 7 - c0;
            o[jr] = (w == 2) ? (v[c0] + v[c0 + 1]) * 0.5f : v[c0];
        }

        // Vector STS; 14*q floats => 16B-aligned for even q, 8B for odd q.
        float* dst = hp + r * 56 + q * 14;
        if ((q & 1) == 0) {
            *(float4*)(dst + 0)  = make_float4(o[0],  o[1],  o[2],  o[3]);
            *(float4*)(dst + 4)  = make_float4(o[4],  o[5],  o[6],  o[7]);
            *(float4*)(dst + 8)  = make_float4(o[8],  o[9],  o[10], o[11]);
            *(float2*)(dst + 12) = make_float2(o[12], o[13]);
        } else {
            *(float2*)(dst + 0)  = make_float2(o[0],  o[1]);
            *(float4*)(dst + 2)  = make_float4(o[2],  o[3],  o[4],  o[5]);
            *(float4*)(dst + 6)  = make_float4(o[6],  o[7],  o[8],  o[9]);
            *(float4*)(dst + 10) = make_float4(o[10], o[11], o[12], o[13]);
        }
    }
    __syncthreads();

    // ---------------- Phase B: vertical pool (smem -> global) ----------------
    float4* __restrict__ out4 = (float4*)outp;
    #pragma unroll
    for (int base = 0; base < N_OUT4; base += 256) {
        const int slot = base + tid;
        if (base + 256 > N_OUT4 && slot >= N_OUT4) break;
        const int i  = slot / 14;
        const int jc = slot - i * 14;
        const int r0 = (i * NUM) / 7;
        const int w  = ((i + 1) * NUM + 6) / 7 - r0;

        const float* a = hp + r0 * 56 + jc * 4;
        const float4 va = *(const float4*)a;
        const float4 vb = *(const float4*)(a + 56);   // valid row or zeroed pad
        const float sc = (w == 2) ? 0.5f : 1.0f;
        const float f  = (w == 2) ? 0.5f : 0.0f;

        float4 res;
        res.x = fmaf(vb.x, f, va.x * sc);
        res.y = fmaf(vb.y, f, va.y * sc);
        res.z = fmaf(vb.z, f, va.z * sc);
        res.w = fmaf(vb.w, f, va.w * sc);
        out4[slot] = res;
    }
}

__global__ __launch_bounds__(256)
void denorm_relu_pool_v2(const float* __restrict__ p24,
                         const float* __restrict__ p32,
                         const float* __restrict__ p48,
                         const float* __restrict__ smean,
                         const float* __restrict__ sstd,
                         float* __restrict__ out)
{
    __shared__ float hp[49 * 56];   // max S=48 rows + 1 zero pad row (10.7 KB)

    const int gnc = blockIdx.x;            // 0..24575 == n*256 + c (global)
    const int grp = gnc >> 13;             // /8192
    const int local = gnc & (NC_PER_GROUP - 1);
    const int tid = threadIdx.x;

    const float mean = __ldg(smean + gnc);
    const float sd   = __ldg(sstd + gnc);
    float* outp = out + (size_t)gnc * N_OUT;

    if (grp == 0) {
        run_group<24>(p24 + (size_t)local * (24 * 24), mean, sd, hp, outp, tid);
    } else if (grp == 1) {
        run_group<32>(p32 + (size_t)local * (32 * 32), mean, sd, hp, outp, tid);
    } else {
        run_group<48>(p48 + (size_t)local * (48 * 48), mean, sd, hp, outp, tid);
    }
}

extern "C" void kernel_launch(void* const* d_in, const int* in_sizes, int n_in,
                              void* d_out, int out_size)
{
    const float* p24   = (const float*)d_in[0];
    const float* p32   = (const float*)d_in[1];
    const float* p48   = (const float*)d_in[2];
    const float* smean = (const float*)d_in[3];
    const float* sstd  = (const float*)d_in[4];
    float* out = (float*)d_out;

    denorm_relu_pool_v2<<<3 * NC_PER_GROUP, 256>>>(p24, p32, p48,
                                                   smean, sstd, out);
}